// round 3
// baseline (speedup 1.0000x reference)
#include <cuda_runtime.h>
#include <math.h>

#define N_NODES 6000
#define DEG 16
#define N_EDGES 96000
#define D_MODEL 256
#define D_MSG 64
#define D_FF 1024
#define N_LAYERS 3
#define RBF_BINS 256

// ---------------- scratch (static device memory; no allocation) ----------------
__device__ float g_x[N_NODES * D_MODEL];      //  6.1 MB
__device__ float g_y[N_EDGES * RBF_BINS];     // 98.3 MB (layer-invariant RBF)
__device__ float g_rhat[N_EDGES * 3];
__device__ float g_xj[N_NODES * D_MSG];
__device__ float g_xi[N_NODES * D_MSG];
__device__ float g_xij[N_EDGES * D_MSG];      // 24.6 MB
__device__ float g_xn[N_NODES * D_MSG];
__device__ float g_h[N_NODES * D_FF];         // 24.6 MB
__device__ float g_partial[256];

// ---------------- embedding gather ----------------
__global__ void embed_kernel(const int* __restrict__ an,
                             const float* __restrict__ emb,
                             float* __restrict__ x) {
    int i = blockIdx.x;
    int c = threadIdx.x;
    x[i * D_MODEL + c] = emb[an[i] * D_MODEL + c];
}

// ---------------- RBF expansion + rhat (once; layer-invariant) ----------------
__global__ void rbf_kernel(const float* __restrict__ r,
                           float* __restrict__ y,
                           float* __restrict__ rhat) {
    int e = blockIdx.x;
    int b = threadIdx.x;
    float rx = r[e * 3 + 0];
    float ry = r[e * 3 + 1];
    float rz = r[e * 3 + 2];
    float d = sqrtf(rx * rx + ry * ry + rz * rz);
    const float step = 8.0f / 255.0f;
    const float gamma = 1.0f / step;
    float t = d - (float)b * step;
    y[e * RBF_BINS + b] = __expf(-gamma * t * t);
    if (b < 3) rhat[e * 3 + b] = r[e * 3 + b] / d;
}

// ---------------- generic tiled SGEMM: C[M,N] = A[M,K] @ B[N,K]^T + epilogue ----
// EPI 0: +bias   EPI 1: silu(+bias)   EPI 2: +bias + xj[src[m]] + xi[m>>4]  (edge mode, N==64)
template <int EPI>
__global__ void gemm_kernel(const float* __restrict__ A,
                            const float* __restrict__ B,
                            float* __restrict__ C,
                            int M, int N, int K,
                            const float* __restrict__ bias,
                            const float* __restrict__ gxj,
                            const float* __restrict__ gxi,
                            const int* __restrict__ srcIdx) {
    __shared__ float As[16][64];
    __shared__ float Bs[16][64];
    int tid = threadIdx.x;
    int m0 = blockIdx.y * 64;
    int n0 = blockIdx.x * 64;
    int lr = tid >> 2;            // 0..63 tile row
    int lk = (tid & 3) << 2;      // 0,4,8,12
    int ty = tid >> 4;            // 0..15
    int tx = tid & 15;            // 0..15
    float acc[4][4] = {};

    for (int k0 = 0; k0 < K; k0 += 16) {
        float4 av = make_float4(0.f, 0.f, 0.f, 0.f);
        if (m0 + lr < M)
            av = *(const float4*)(A + (size_t)(m0 + lr) * K + k0 + lk);
        float4 bv = *(const float4*)(B + (size_t)(n0 + lr) * K + k0 + lk);
        As[lk + 0][lr] = av.x; As[lk + 1][lr] = av.y;
        As[lk + 2][lr] = av.z; As[lk + 3][lr] = av.w;
        Bs[lk + 0][lr] = bv.x; Bs[lk + 1][lr] = bv.y;
        Bs[lk + 2][lr] = bv.z; Bs[lk + 3][lr] = bv.w;
        __syncthreads();
#pragma unroll
        for (int kk = 0; kk < 16; kk++) {
            float4 a4 = *(const float4*)&As[kk][ty << 2];
            float4 b4 = *(const float4*)&Bs[kk][tx << 2];
            float ar[4] = {a4.x, a4.y, a4.z, a4.w};
            float br[4] = {b4.x, b4.y, b4.z, b4.w};
#pragma unroll
            for (int i = 0; i < 4; i++)
#pragma unroll
                for (int j = 0; j < 4; j++)
                    acc[i][j] = fmaf(ar[i], br[j], acc[i][j]);
        }
        __syncthreads();
    }

#pragma unroll
    for (int i = 0; i < 4; i++) {
        int m = m0 + (ty << 2) + i;
        if (m >= M) continue;
        int sidx = 0;
        if (EPI == 2) sidx = srcIdx[m];
#pragma unroll
        for (int j = 0; j < 4; j++) {
            int n = n0 + (tx << 2) + j;
            float v = acc[i][j] + bias[n];
            if (EPI == 1) v = __fdividef(v, 1.0f + __expf(-v));  // silu
            if (EPI == 2) v += gxj[sidx * 64 + n] + gxi[(m >> 4) * 64 + n];
            C[(size_t)m * N + n] = v;
        }
    }
}

// ---------------- per-node triplet attention (the collapsed stage) ----------------
// One block per node. 240 ordered edge pairs (p,q), p!=q, edges = node*16+{0..15}.
// logit_pq = sum_k attn[k] * silu(T_k(c_pq) + xij_p[k] + xij_q[k])
// a = softmax over p (fixed q); w_p = sum_q a_pq; xn = sum_p w_p * xij_p.
__global__ void triplet_kernel(const float* __restrict__ xij,
                               const float* __restrict__ rhat,
                               const float* __restrict__ attn,
                               float* __restrict__ xn) {
    __shared__ float sx[64][17];   // [channel][edge-slot], padded
    __shared__ float rh[16][3];
    __shared__ float sat[64];
    __shared__ float sl[16][16];   // [q][p-slot] logits
    __shared__ float mq[16], zi[16], wp[16];

    int node = blockIdx.x;
    int t = threadIdx.x;
    const float* xb = xij + (size_t)node * 16 * 64;

    for (int idx = t; idx < 1024; idx += 256) {
        int p = idx >> 6, k = idx & 63;
        sx[k][p] = xb[idx];
    }
    if (t < 48) rh[t / 3][t % 3] = rhat[node * 48 + t];
    if (t < 64) sat[t] = attn[t];
    __syncthreads();

    if (t < 240) {
        int q = t / 15;
        int ps = t % 15;
        int p = ps + (ps >= q ? 1 : 0);
        float c = rh[p][0] * rh[q][0] + rh[p][1] * rh[q][1] + rh[p][2] * rh[q][2];
        c = fminf(fmaxf(c, -1.0f + 1e-6f), 1.0f - 1e-6f);
        float c2 = 2.0f * c;
        float t0 = 1.0f, t1 = c;
        float acc;
        {   // k = 0, z = 1
            float s = 1.0f + sx[0][p] + sx[0][q];
            float si = __fdividef(s, 1.0f + __expf(-s));
            acc = sat[0] * si;
        }
#pragma unroll
        for (int k = 1; k < 64; k++) {
            float z = t1;
            float s = z + sx[k][p] + sx[k][q];
            float si = __fdividef(s, 1.0f + __expf(-s));
            acc = fmaf(sat[k], si, acc);
            float tn = fmaf(c2, t1, -t0);
            t0 = t1; t1 = tn;
        }
        sl[q][ps] = acc;
    }
    __syncthreads();

    if (t < 16) {      // per-q softmax normalizers
        int q = t;
        float m = -1e30f;
#pragma unroll
        for (int ps = 0; ps < 15; ps++) m = fmaxf(m, sl[q][ps]);
        float z = 0.0f;
#pragma unroll
        for (int ps = 0; ps < 15; ps++) z += __expf(sl[q][ps] - m);
        mq[q] = m;
        zi[q] = __fdividef(1.0f, z);
    }
    __syncthreads();

    if (t < 16) {      // w_p = sum_q a_pq  (deterministic fixed order)
        int p = t;
        float w = 0.0f;
#pragma unroll
        for (int q = 0; q < 16; q++) {
            if (q == p) continue;
            int ps = (p < q) ? p : p - 1;
            w += __expf(sl[q][ps] - mq[q]) * zi[q];
        }
        wp[p] = w;
    }
    __syncthreads();

    if (t < 64) {      // xn[node][k] = sum_p w_p * xij_p[k]
        int k = t;
        float acc = 0.0f;
#pragma unroll
        for (int p = 0; p < 16; p++) acc = fmaf(wp[p], sx[k][p], acc);
        xn[node * 64 + k] = acc;
    }
}

// ---------------- output head: mean(x @ Wfc^T) + bfc, deterministic 2-stage ----
__global__ void out_partial_kernel(const float* __restrict__ x,
                                   const float* __restrict__ Wfc,
                                   float* __restrict__ partial) {
    __shared__ float red[256];
    float acc = 0.0f;
    for (int idx = blockIdx.x * 256 + threadIdx.x; idx < N_NODES * D_MODEL;
         idx += 256 * 256)
        acc = fmaf(x[idx], Wfc[idx & 255], acc);
    red[threadIdx.x] = acc;
    __syncthreads();
    for (int s = 128; s > 0; s >>= 1) {
        if (threadIdx.x < s) red[threadIdx.x] += red[threadIdx.x + s];
        __syncthreads();
    }
    if (threadIdx.x == 0) partial[blockIdx.x] = red[0];
}

__global__ void out_final_kernel(const float* __restrict__ partial,
                                 const float* __restrict__ bfc,
                                 float* __restrict__ out) {
    if (threadIdx.x == 0) {
        float s = 0.0f;
        for (int i = 0; i < 256; i++) s += partial[i];
        out[0] = s / (float)N_NODES + bfc[0];
    }
}

// ---------------- launcher ----------------
extern "C" void kernel_launch(void* const* d_in, const int* in_sizes, int n_in,
                              void* d_out, int out_size) {
    const float* r     = (const float*)d_in[0];
    const int*   an    = (const int*)d_in[1];
    const int*   src   = (const int*)d_in[2];
    const float* emb   = (const float*)d_in[6];
    const float* Wsrc  = (const float*)d_in[7];
    const float* bsrc  = (const float*)d_in[8];
    const float* Wdst  = (const float*)d_in[9];
    const float* bdst  = (const float*)d_in[10];
    const float* Wedge = (const float*)d_in[11];
    const float* bedge = (const float*)d_in[12];
    const float* attn  = (const float*)d_in[13];
    const float* W1    = (const float*)d_in[14];
    const float* b1    = (const float*)d_in[15];
    const float* W2    = (const float*)d_in[16];
    const float* b2    = (const float*)d_in[17];
    const float* Wfc   = (const float*)d_in[18];
    const float* bfc   = (const float*)d_in[19];
    float* out = (float*)d_out;

    float *x, *y, *rhat, *xj, *xi, *xij, *xn, *h, *part;
    cudaGetSymbolAddress((void**)&x,    g_x);
    cudaGetSymbolAddress((void**)&y,    g_y);
    cudaGetSymbolAddress((void**)&rhat, g_rhat);
    cudaGetSymbolAddress((void**)&xj,   g_xj);
    cudaGetSymbolAddress((void**)&xi,   g_xi);
    cudaGetSymbolAddress((void**)&xij,  g_xij);
    cudaGetSymbolAddress((void**)&xn,   g_xn);
    cudaGetSymbolAddress((void**)&h,    g_h);
    cudaGetSymbolAddress((void**)&part, g_partial);

    embed_kernel<<<N_NODES, 256>>>(an, emb, x);
    rbf_kernel<<<N_EDGES, 256>>>(r, y, rhat);

    const int MB_NODE = (N_NODES + 63) / 64;   // 94
    const int MB_EDGE = N_EDGES / 64;          // 1500

    for (int l = 0; l < N_LAYERS; l++) {
        // xj = x @ Wsrc^T + bsrc ; xi = x @ Wdst^T + bdst
        gemm_kernel<0><<<dim3(1, MB_NODE), 256>>>(
            x, Wsrc + l * 64 * 256, xj, N_NODES, 64, 256,
            bsrc + l * 64, nullptr, nullptr, nullptr);
        gemm_kernel<0><<<dim3(1, MB_NODE), 256>>>(
            x, Wdst + l * 64 * 256, xi, N_NODES, 64, 256,
            bdst + l * 64, nullptr, nullptr, nullptr);
        // xij = y @ Wedge^T + bedge + xj[src] + xi[dst]
        gemm_kernel<2><<<dim3(1, MB_EDGE), 256>>>(
            y, Wedge + l * 64 * 256, xij, N_EDGES, 64, 256,
            bedge + l * 64, xj, xi, src);
        // per-node triplet attention -> xn
        triplet_kernel<<<N_NODES, 256>>>(xij, rhat, attn + l * 64, xn);
        // FFN
        gemm_kernel<1><<<dim3(16, MB_NODE), 256>>>(
            xn, W1 + l * D_FF * 64, h, N_NODES, D_FF, 64,
            b1 + l * D_FF, nullptr, nullptr, nullptr);
        gemm_kernel<0><<<dim3(4, MB_NODE), 256>>>(
            h, W2 + l * D_MODEL * D_FF, x, N_NODES, D_MODEL, D_FF,
            b2 + l * D_MODEL, nullptr, nullptr, nullptr);
    }

    out_partial_kernel<<<256, 256>>>(x, Wfc, part);
    out_final_kernel<<<1, 32>>>(part, bfc, out);
}

// round 5
// speedup vs baseline: 1.2784x; 1.2784x over previous
#include <cuda_runtime.h>
#include <math.h>

#define N_NODES 6000
#define DEG 16
#define N_EDGES 96000
#define D_MODEL 256
#define D_MSG 64
#define D_FF 1024
#define N_LAYERS 3
#define RBF_BINS 256

// ---------------- scratch (static device memory; no allocation) ----------------
__device__ float g_x[N_NODES * D_MODEL];
__device__ float g_rhat[N_EDGES * 3];
__device__ float g_xj[N_NODES * D_MSG];
__device__ float g_xi[N_NODES * D_MSG];
__device__ float g_xij[N_EDGES * D_MSG];
__device__ float g_xn[N_NODES * D_MSG];
__device__ float g_h[N_NODES * D_FF];
__device__ float g_partial[256];

// ---------------- embedding gather ----------------
__global__ void embed_kernel(const int* __restrict__ an,
                             const float* __restrict__ emb,
                             float* __restrict__ x) {
    int i = blockIdx.x;
    int c = threadIdx.x;
    x[i * D_MODEL + c] = emb[an[i] * D_MODEL + c];
}

// ---------------- rhat (once) ----------------
__global__ void rhat_kernel(const float* __restrict__ r,
                            float* __restrict__ rhat) {
    int e = blockIdx.x * blockDim.x + threadIdx.x;
    if (e >= N_EDGES) return;
    float rx = r[e * 3 + 0], ry = r[e * 3 + 1], rz = r[e * 3 + 2];
    float d = sqrtf(rx * rx + ry * ry + rz * rz);
    rhat[e * 3 + 0] = rx / d;
    rhat[e * 3 + 1] = ry / d;
    rhat[e * 3 + 2] = rz / d;
}

// ---------------- fused windowed-RBF edge kernel -------------------------------
// xij[e][ch] = sum_b exp(-g*(d_e - b*step)^2) * Wedge[ch][b] + bedge[ch]
//            + xj[src[e]][ch] + xi[dst][ch]
// Gaussian support: only 64 bins around d contribute (>8e-14 outside).
// Block: 256 threads, 16 edges (= one dst node) per group, grid-stride over nodes.
#define EDGE_WPITCH 68
#define EDGE_SMEM_BYTES (256 * EDGE_WPITCH * 4 + 16 * 64 * 4 + 16 * 4 * 3)

__global__ void edge_kernel(const float* __restrict__ r,
                            const int* __restrict__ src,
                            const float* __restrict__ We,     // [64,256]
                            const float* __restrict__ bedge,  // [64]
                            const float* __restrict__ xj,
                            const float* __restrict__ xi,
                            float* __restrict__ xij) {
    extern __shared__ float sm[];
    float* sWt = sm;                        // [256][68] transposed Wedge
    float* sy = sm + 256 * EDGE_WPITCH;     // [16][64]
    int* sb0 = (int*)(sy + 16 * 64);        // [16]
    int* ssrc = sb0 + 16;                   // [16]
    float* sd = (float*)(ssrc + 16);        // [16]

    int t = threadIdx.x;
    // load Wedge transposed: sWt[b][ch]
    for (int idx = t; idx < 64 * 256; idx += 256) {
        int ch = idx >> 8, b = idx & 255;
        sWt[b * EDGE_WPITCH + ch] = We[idx];
    }
    int e_sub = t >> 4;      // 0..15
    int chv = t & 15;        // channel group (4 ch)
    float4 bed = *(const float4*)&bedge[chv * 4];
    const float inv_step = 255.0f / 8.0f;
    const float step = 8.0f / 255.0f;
    const float gamma = inv_step;

    for (int g = blockIdx.x; g < N_NODES; g += gridDim.x) {
        __syncthreads();                    // prior group fully consumed
        if (t < 16) {
            int e = g * 16 + t;
            float rx = r[e * 3 + 0], ry = r[e * 3 + 1], rz = r[e * 3 + 2];
            float d = sqrtf(rx * rx + ry * ry + rz * rz);
            int cb = (int)(d * inv_step + 0.5f);
            int b0 = cb - 32;
            b0 = b0 < 0 ? 0 : (b0 > 192 ? 192 : b0);
            sb0[t] = b0;
            sd[t] = d;
            ssrc[t] = src[e];
        }
        __syncthreads();
        {   // y window: thread computes 4 bins of edge (t>>4)
            float d = sd[e_sub];
            int b0 = sb0[e_sub];
            int jb = chv * 4;
#pragma unroll
            for (int i = 0; i < 4; i++) {
                float tt = d - (float)(b0 + jb + i) * step;
                sy[e_sub * 64 + jb + i] = __expf(-gamma * tt * tt);
            }
        }
        __syncthreads();
        {
            int b0 = sb0[e_sub];
            const float* wp = sWt + (size_t)b0 * EDGE_WPITCH + chv * 4;
            const float* yp = sy + e_sub * 64;
            float4 acc = bed;
#pragma unroll 16
            for (int j = 0; j < 64; j++) {
                float yv = yp[j];
                float4 w = *(const float4*)(wp + (size_t)j * EDGE_WPITCH);
                acc.x = fmaf(yv, w.x, acc.x);
                acc.y = fmaf(yv, w.y, acc.y);
                acc.z = fmaf(yv, w.z, acc.z);
                acc.w = fmaf(yv, w.w, acc.w);
            }
            int sidx = ssrc[e_sub];
            float4 aj = *(const float4*)&xj[sidx * 64 + chv * 4];
            float4 ai = *(const float4*)&xi[g * 64 + chv * 4];
            acc.x += aj.x + ai.x;
            acc.y += aj.y + ai.y;
            acc.z += aj.z + ai.z;
            acc.w += aj.w + ai.w;
            *(float4*)&xij[(size_t)(g * 16 + e_sub) * 64 + chv * 4] = acc;
        }
    }
}

// ---------------- SGEMM: C[M,N] = A[M,K] @ B[N,K]^T + bias, tile 64x64, 8x4/thr
// EPI 0: +bias   EPI 1: silu(+bias)   EPI 3: dual node-proj (bx selects B/bias/C)
template <int EPI>
__global__ void gemm64(const float* __restrict__ A,
                       const float* __restrict__ B,
                       float* __restrict__ C,
                       int M, int N, int K,
                       const float* __restrict__ bias,
                       const float* __restrict__ B2,
                       const float* __restrict__ bias2,
                       float* __restrict__ C2) {
    __shared__ float As[32][64];
    __shared__ float Bs[32][64];
    int t = threadIdx.x;
    int n0 = blockIdx.x * 64;
    int m0 = blockIdx.y * 64;
    if (EPI == 3) {
        if (blockIdx.x == 1) { B = B2; bias = bias2; C = C2; }
        n0 = 0;
    }
    int r = t & 63;
    int kb = (t >> 6) * 16;
    int rg8 = (t >> 4) * 8;
    if (rg8 >= 64) rg8 -= 64;
    int cg4 = (t & 15) * 4;

    float acc[8][4];
#pragma unroll
    for (int i = 0; i < 8; i++)
#pragma unroll
        for (int j = 0; j < 4; j++) acc[i][j] = 0.0f;

    int rowA = m0 + r;
    bool okA = rowA < M;
    const float* Ap = A + (size_t)(okA ? rowA : 0) * K + kb;
    const float* Bp = B + (size_t)(n0 + r) * K + kb;

    for (int k0 = 0; k0 < K; k0 += 32) {
        float4 av[4], bv[4];
#pragma unroll
        for (int i = 0; i < 4; i++) {
            av[i] = okA ? *(const float4*)(Ap + k0 + i * 4)
                        : make_float4(0.f, 0.f, 0.f, 0.f);
            bv[i] = *(const float4*)(Bp + k0 + i * 4);
        }
        __syncthreads();
#pragma unroll
        for (int i = 0; i < 4; i++) {
            As[kb + i * 4 + 0][r] = av[i].x;
            As[kb + i * 4 + 1][r] = av[i].y;
            As[kb + i * 4 + 2][r] = av[i].z;
            As[kb + i * 4 + 3][r] = av[i].w;
            Bs[kb + i * 4 + 0][r] = bv[i].x;
            Bs[kb + i * 4 + 1][r] = bv[i].y;
            Bs[kb + i * 4 + 2][r] = bv[i].z;
            Bs[kb + i * 4 + 3][r] = bv[i].w;
        }
        __syncthreads();
#pragma unroll 8
        for (int kk = 0; kk < 32; kk++) {
            float4 a0 = *(const float4*)&As[kk][rg8];
            float4 a1 = *(const float4*)&As[kk][rg8 + 4];
            float4 b = *(const float4*)&Bs[kk][cg4];
            float ar[8] = {a0.x, a0.y, a0.z, a0.w, a1.x, a1.y, a1.z, a1.w};
            float br[4] = {b.x, b.y, b.z, b.w};
#pragma unroll
            for (int i = 0; i < 8; i++)
#pragma unroll
                for (int j = 0; j < 4; j++)
                    acc[i][j] = fmaf(ar[i], br[j], acc[i][j]);
        }
    }
    __syncthreads();

    float4 b4 = *(const float4*)&bias[n0 + cg4];
    float bb[4] = {b4.x, b4.y, b4.z, b4.w};
#pragma unroll
    for (int i = 0; i < 8; i++) {
        int m = m0 + rg8 + i;
        if (m >= M) continue;
        float4 v;
        float* vp = &v.x;
#pragma unroll
        for (int j = 0; j < 4; j++) {
            float s = acc[i][j] + bb[j];
            if (EPI == 1) s = __fdividef(s, 1.0f + __expf(-s));
            vp[j] = s;
        }
        *(float4*)&C[(size_t)m * N + n0 + cg4] = v;
    }
}

// ---------------- per-node triplet attention ----------------
__global__ void triplet_kernel(const float* __restrict__ xij,
                               const float* __restrict__ rhat,
                               const float* __restrict__ attn,
                               float* __restrict__ xn) {
    __shared__ float sx[64][17];
    __shared__ float rh[16][3];
    __shared__ float sat[64];
    __shared__ float sl[16][16];
    __shared__ float mq[16], zi[16], wp[16];

    int node = blockIdx.x;
    int t = threadIdx.x;
    const float* xb = xij + (size_t)node * 16 * 64;

    for (int idx = t; idx < 1024; idx += 256) {
        int p = idx >> 6, k = idx & 63;
        sx[k][p] = xb[idx];
    }
    if (t < 48) rh[t / 3][t % 3] = rhat[node * 48 + t];
    if (t < 64) sat[t] = attn[t];
    __syncthreads();

    if (t < 240) {
        int q = t / 15;
        int ps = t % 15;
        int p = ps + (ps >= q ? 1 : 0);
        float c = rh[p][0] * rh[q][0] + rh[p][1] * rh[q][1] + rh[p][2] * rh[q][2];
        c = fminf(fmaxf(c, -1.0f + 1e-6f), 1.0f - 1e-6f);
        float c2 = 2.0f * c;
        float t0 = 1.0f, t1 = c;
        float acc;
        {
            float s = 1.0f + sx[0][p] + sx[0][q];
            float si = __fdividef(s, 1.0f + __expf(-s));
            acc = sat[0] * si;
        }
#pragma unroll
        for (int k = 1; k < 64; k++) {
            float z = t1;
            float s = z + sx[k][p] + sx[k][q];
            float si = __fdividef(s, 1.0f + __expf(-s));
            acc = fmaf(sat[k], si, acc);
            float tn = fmaf(c2, t1, -t0);
            t0 = t1; t1 = tn;
        }
        sl[q][ps] = acc;
    }
    __syncthreads();

    if (t < 16) {
        int q = t;
        float m = -1e30f;
#pragma unroll
        for (int ps = 0; ps < 15; ps++) m = fmaxf(m, sl[q][ps]);
        float z = 0.0f;
#pragma unroll
        for (int ps = 0; ps < 15; ps++) z += __expf(sl[q][ps] - m);
        mq[q] = m;
        zi[q] = __fdividef(1.0f, z);
    }
    __syncthreads();

    if (t < 16) {
        int p = t;
        float w = 0.0f;
#pragma unroll
        for (int q = 0; q < 16; q++) {
            if (q == p) continue;
            int ps = (p < q) ? p : p - 1;
            w += __expf(sl[q][ps] - mq[q]) * zi[q];
        }
        wp[p] = w;
    }
    __syncthreads();

    if (t < 64) {
        int k = t;
        float acc = 0.0f;
#pragma unroll
        for (int p = 0; p < 16; p++) acc = fmaf(wp[p], sx[k][p], acc);
        xn[node * 64 + k] = acc;
    }
}

// ---------------- output head ----------------
__global__ void out_partial_kernel(const float* __restrict__ x,
                                   const float* __restrict__ Wfc,
                                   float* __restrict__ partial) {
    __shared__ float red[256];
    float acc = 0.0f;
    for (int idx = blockIdx.x * 256 + threadIdx.x; idx < N_NODES * D_MODEL;
         idx += 256 * 256)
        acc = fmaf(x[idx], Wfc[idx & 255], acc);
    red[threadIdx.x] = acc;
    __syncthreads();
    for (int s = 128; s > 0; s >>= 1) {
        if (threadIdx.x < s) red[threadIdx.x] += red[threadIdx.x + s];
        __syncthreads();
    }
    if (threadIdx.x == 0) partial[blockIdx.x] = red[0];
}

__global__ void out_final_kernel(const float* __restrict__ partial,
                                 const float* __restrict__ bfc,
                                 float* __restrict__ out) {
    if (threadIdx.x == 0) {
        float s = 0.0f;
        for (int i = 0; i < 256; i++) s += partial[i];
        out[0] = s / (float)N_NODES + bfc[0];
    }
}

// ---------------- launcher ----------------
extern "C" void kernel_launch(void* const* d_in, const int* in_sizes, int n_in,
                              void* d_out, int out_size) {
    const float* r     = (const float*)d_in[0];
    const int*   an    = (const int*)d_in[1];
    const int*   src   = (const int*)d_in[2];
    const float* emb   = (const float*)d_in[6];
    const float* Wsrc  = (const float*)d_in[7];
    const float* bsrc  = (const float*)d_in[8];
    const float* Wdst  = (const float*)d_in[9];
    const float* bdst  = (const float*)d_in[10];
    const float* Wedge = (const float*)d_in[11];
    const float* bedge = (const float*)d_in[12];
    const float* attn  = (const float*)d_in[13];
    const float* W1    = (const float*)d_in[14];
    const float* b1    = (const float*)d_in[15];
    const float* W2    = (const float*)d_in[16];
    const float* b2    = (const float*)d_in[17];
    const float* Wfc   = (const float*)d_in[18];
    const float* bfc   = (const float*)d_in[19];
    float* out = (float*)d_out;

    float *x, *rhat, *xj, *xi, *xij, *xn, *h, *part;
    cudaGetSymbolAddress((void**)&x,    g_x);
    cudaGetSymbolAddress((void**)&rhat, g_rhat);
    cudaGetSymbolAddress((void**)&xj,   g_xj);
    cudaGetSymbolAddress((void**)&xi,   g_xi);
    cudaGetSymbolAddress((void**)&xij,  g_xij);
    cudaGetSymbolAddress((void**)&xn,   g_xn);
    cudaGetSymbolAddress((void**)&h,    g_h);
    cudaGetSymbolAddress((void**)&part, g_partial);

    cudaFuncSetAttribute(edge_kernel,
                         cudaFuncAttributeMaxDynamicSharedMemorySize,
                         EDGE_SMEM_BYTES);

    embed_kernel<<<N_NODES, 256>>>(an, emb, x);
    rhat_kernel<<<(N_EDGES + 255) / 256, 256>>>(r, rhat);

    const int MB_NODE = (N_NODES + 63) / 64;   // 94

    for (int l = 0; l < N_LAYERS; l++) {
        // xj = x@Wsrc^T+bsrc and xi = x@Wdst^T+bdst in one dual launch
        gemm64<3><<<dim3(2, MB_NODE), 128>>>(
            x, Wsrc + l * 64 * 256, xj, N_NODES, 64, 256, bsrc + l * 64,
            Wdst + l * 64 * 256, bdst + l * 64, xi);
        // fused windowed-RBF edge features + gathers
        edge_kernel<<<444, 256, EDGE_SMEM_BYTES>>>(
            r, src, Wedge + l * 64 * 256, bedge + l * 64, xj, xi, xij);
        // per-node triplet attention -> xn
        triplet_kernel<<<N_NODES, 256>>>(xij, rhat, attn + l * 64, xn);
        // FFN
        gemm64<1><<<dim3(16, MB_NODE), 128>>>(
            xn, W1 + l * D_FF * 64, h, N_NODES, D_FF, 64, b1 + l * D_FF,
            nullptr, nullptr, nullptr);
        gemm64<0><<<dim3(4, MB_NODE), 128>>>(
            h, W2 + l * D_MODEL * D_FF, x, N_NODES, D_MODEL, D_FF,
            b2 + l * D_MODEL, nullptr, nullptr, nullptr);
    }

    out_partial_kernel<<<256, 256>>>(x, Wfc, part);
    out_final_kernel<<<1, 32>>>(part, bfc, out);
}